// round 1
// baseline (speedup 1.0000x reference)
#include <cuda_runtime.h>
#include <stdint.h>
#include <math.h>

#define MAXN    131072
#define KTOP    4096
#define MAXDET  100
#define THRESH  0.5f
#define NMSTHR  0.5f

// ---------------- static device scratch (no allocations allowed) ----------------
__device__ float              g_score[MAXN];     // cand value (max score or -1)
__device__ unsigned int       g_key[MAXN];       // monotone sort key of g_score
__device__ float4             g_box[MAXN];       // decoded, clipped boxes (x1,y1,x2,y2)
__device__ int                g_cls[MAXN];       // argmax class
__device__ int                g_hist1[65536];
__device__ int                g_hist2[65536];
__device__ int                g_cnt[4];          // [0]=cnt_gt, [1]=cnt_eq
__device__ int                g_selinfo[2];      // [0]=bucket B, [1]=G1 (count above bucket)
__device__ unsigned int       g_Tkey;            // threshold key (K-th largest)
__device__ int                g_G;               // count of keys strictly > Tkey
__device__ unsigned long long g_sel[KTOP];       // composite (key<<32)|~idx
__device__ int                g_eq[KTOP];        // indices with key == Tkey
__device__ float4             g_cbox[KTOP];
__device__ float              g_cscore[KTOP];
__device__ int                g_ccls[KTOP];
__device__ unsigned long long g_mask[(size_t)KTOP * 64];  // NMS suppression bitmask

__device__ __forceinline__ unsigned int fkey(float f) {
    unsigned int u = __float_as_uint(f);
    return u ^ ((u >> 31) ? 0xFFFFFFFFu : 0x80000000u);  // monotone float->uint
}

// ---------------- kernel 0: zero histograms + counters ----------------
__global__ void k_zero() {
    int i = blockIdx.x * blockDim.x + threadIdx.x;
    if (i < 65536) { g_hist1[i] = 0; g_hist2[i] = 0; }
    if (i < 4) g_cnt[i] = 0;
}

// ---------------- kernel 1: per-anchor score/argmax/decode + histogram ----------------
__global__ void k_prep(const float* __restrict__ reg, const float* __restrict__ cls,
                       const float* __restrict__ anc, int N, int C, float Wm1, float Hm1) {
    int i = blockIdx.x * blockDim.x + threadIdx.x;
    if (i >= N) return;

    // argmax over classes (first-occurrence, matching jnp.argmax)
    const float2* c2 = reinterpret_cast<const float2*>(cls + (size_t)i * C);
    float best = -1e30f; int bc = 0;
    int half = C >> 1;
    for (int k = 0; k < half; k++) {
        float2 v = c2[k];
        if (v.x > best) { best = v.x; bc = 2 * k; }
        if (v.y > best) { best = v.y; bc = 2 * k + 1; }
    }
    if (C & 1) {
        float v = cls[(size_t)i * C + C - 1];
        if (v > best) { best = v; bc = C - 1; }
    }

    // decode box (anchors are y1,x1,y2,x2; reg is dy,dx,dh,dw)
    float a0 = anc[i * 4 + 0], a1 = anc[i * 4 + 1], a2 = anc[i * 4 + 2], a3 = anc[i * 4 + 3];
    float r0 = reg[i * 4 + 0], r1 = reg[i * 4 + 1], r2 = reg[i * 4 + 2], r3 = reg[i * 4 + 3];
    float ya = (a0 + a2) * 0.5f, xa = (a1 + a3) * 0.5f;
    float ha = a2 - a0, wa = a3 - a1;
    float w = expf(r3) * wa, h = expf(r2) * ha;
    float yc = r0 * ha + ya, xc = r1 * wa + xa;
    float x1 = fmaxf(xc - w * 0.5f, 0.0f);
    float y1 = fmaxf(yc - h * 0.5f, 0.0f);
    float x2 = fminf(xc + w * 0.5f, Wm1);
    float y2 = fminf(yc + h * 0.5f, Hm1);
    g_box[i] = make_float4(x1, y1, x2, y2);

    float cand = (best > THRESH) ? best : -1.0f;
    g_score[i] = cand;
    g_cls[i] = bc;
    unsigned int k = fkey(cand);
    g_key[i] = k;
    atomicAdd(&g_hist1[k >> 16], 1);
}

// ---------------- kernel 2/4: find bucket containing K-th largest ----------------
__global__ void k_find(int level) {
    __shared__ int seg[1024];
    __shared__ int suf[1024];
    const int* hist = (level == 0) ? g_hist1 : g_hist2;
    int base = (level == 0) ? 0 : g_selinfo[1];
    int t = threadIdx.x;
    int b0 = t * 64;
    int s = 0;
#pragma unroll
    for (int j = 0; j < 64; j++) s += hist[b0 + j];
    seg[t] = s; suf[t] = s;
    __syncthreads();
    // inclusive suffix sum over segments
    for (int off = 1; off < 1024; off <<= 1) {
        int v = (t + off < 1024) ? suf[t + off] : 0;
        __syncthreads();
        suf[t] += v;
        __syncthreads();
    }
    int exc = (t < 1023) ? suf[t + 1] : 0;       // keys in buckets above this segment
    int cg = exc + base;
    if (cg < KTOP && cg + seg[t] >= KTOP) {       // unique crossing segment
        int acc = cg;
        for (int b = b0 + 63; b >= b0; b--) {
            int h = hist[b];
            if (acc < KTOP && acc + h >= KTOP) {
                if (level == 0) { g_selinfo[0] = b; g_selinfo[1] = acc; }
                else { g_Tkey = ((unsigned int)g_selinfo[0] << 16) | (unsigned int)b; g_G = acc; }
                break;
            }
            acc += h;
        }
    }
}

// ---------------- kernel 3: second-level histogram ----------------
__global__ void k_hist2(int N) {
    int i = blockIdx.x * blockDim.x + threadIdx.x;
    if (i >= N) return;
    unsigned int k = g_key[i];
    if ((int)(k >> 16) == g_selinfo[0]) atomicAdd(&g_hist2[k & 0xFFFFu], 1);
}

// ---------------- kernel 5: compaction ----------------
__global__ void k_compact(int N) {
    int i = blockIdx.x * blockDim.x + threadIdx.x;
    if (i >= N) return;
    unsigned int k = g_key[i];
    unsigned int T = g_Tkey;
    if (k > T) {
        int p = atomicAdd(&g_cnt[0], 1);
        g_sel[p] = ((unsigned long long)k << 32) | (unsigned int)(~(unsigned int)i);
    } else if (k == T) {
        int p = atomicAdd(&g_cnt[1], 1);
        if (p < KTOP) g_eq[p] = i;
    }
}

// ---------------- kernel 6: fill equal-key slots (lowest indices first) ----------------
__global__ void k_fill_eq() {
    __shared__ int red[256];
    int t = threadIdx.x;
    int need = KTOP - g_G;
    int E = g_cnt[1]; if (E > KTOP) E = KTOP;
    unsigned int T = g_Tkey;
    for (int r = 0; r < need; r++) {
        int m = 0x7FFFFFFF;
        for (int j = t; j < E; j += 256) m = min(m, g_eq[j]);
        red[t] = m;
        __syncthreads();
        for (int off = 128; off; off >>= 1) {
            if (t < off) red[t] = min(red[t], red[t + off]);
            __syncthreads();
        }
        int minv = red[0];
        for (int j = t; j < E; j += 256) if (g_eq[j] == minv) g_eq[j] = 0x7FFFFFFF;
        if (t == 0) g_sel[g_G + r] = ((unsigned long long)T << 32) | (unsigned int)(~(unsigned int)minv);
        __syncthreads();
    }
}

// ---------------- kernel 7: bitonic sort of 4096 composite keys, descending ----------------
__global__ void k_sort() {
    __shared__ unsigned long long sh[KTOP];
    int t = threadIdx.x;
    for (int i = t; i < KTOP; i += 1024) sh[i] = g_sel[i];
    __syncthreads();
    for (int k = 2; k <= KTOP; k <<= 1) {
        for (int j = k >> 1; j > 0; j >>= 1) {
            for (int i = t; i < KTOP; i += 1024) {
                int ixj = i ^ j;
                if (ixj > i) {
                    bool up = (i & k) != 0;  // ascending sub-block => overall descending
                    unsigned long long a = sh[i], b = sh[ixj];
                    if (up ? (a > b) : (a < b)) { sh[i] = b; sh[ixj] = a; }
                }
            }
            __syncthreads();
        }
    }
    for (int i = t; i < KTOP; i += 1024) g_sel[i] = sh[i];
}

// ---------------- kernel 8: gather candidates ----------------
__global__ void k_gather() {
    int j = blockIdx.x * blockDim.x + threadIdx.x;
    if (j >= KTOP) return;
    unsigned long long v = g_sel[j];
    int idx = (int)(~(unsigned int)v);
    g_cbox[j] = g_box[idx];
    g_cscore[j] = g_score[idx];
    g_ccls[j] = g_cls[idx];
}

// ---------------- kernel 9: NMS suppression bitmask (4096x4096) ----------------
__global__ void k_mask() {
    __shared__ float4 cb[64];
    int t = threadIdx.x;
    int col0 = blockIdx.x * 64, row0 = blockIdx.y * 64;
    cb[t] = g_cbox[col0 + t];
    __syncthreads();
    int i = row0 + t;
    float4 bi = g_cbox[i];
    float areai = fmaxf(bi.z - bi.x, 0.0f) * fmaxf(bi.w - bi.y, 0.0f);
    unsigned long long bits = 0;
#pragma unroll 4
    for (int c = 0; c < 64; c++) {
        int j = col0 + c;
        if (j > i) {
            float4 bj = cb[c];
            float ix1 = fmaxf(bi.x, bj.x), iy1 = fmaxf(bi.y, bj.y);
            float ix2 = fminf(bi.z, bj.z), iy2 = fminf(bi.w, bj.w);
            float inter = fmaxf(ix2 - ix1, 0.0f) * fmaxf(iy2 - iy1, 0.0f);
            float areaj = fmaxf(bj.z - bj.x, 0.0f) * fmaxf(bj.w - bj.y, 0.0f);
            float uni = areai + areaj - inter;
            float iou = inter / fmaxf(uni, 1e-8f);
            if (iou > NMSTHR) bits |= 1ull << c;
        }
    }
    g_mask[(size_t)i * 64 + blockIdx.x] = bits;
}

// ---------------- kernel 10: sequential greedy scan (1 warp) + output ----------------
__global__ void k_scan(float* __restrict__ out, int out_size) {
    int lane = threadIdx.x;
    __shared__ int keep[MAXDET];
    unsigned long long r0 = 0, r1 = 0;
    int w0 = lane, w1 = lane + 32;
    // initialize removal bitmap: invalid (score <= THRESH) candidates are pre-removed
    for (int b = 0; b < 64; b++) {
        if (g_cscore[w0 * 64 + b] <= THRESH) r0 |= 1ull << b;
        if (g_cscore[w1 * 64 + b] <= THRESH) r1 |= 1ull << b;
    }
    int cnt = 0;
    while (true) {
        unsigned long long m0 = ~r0, m1 = ~r1;
        int c0 = m0 ? (w0 * 64 + (__ffsll((long long)m0) - 1)) : 0x7FFFFFFF;
        int c1 = m1 ? (w1 * 64 + (__ffsll((long long)m1) - 1)) : 0x7FFFFFFF;
        int c = min(c0, c1);
#pragma unroll
        for (int off = 16; off; off >>= 1) c = min(c, __shfl_xor_sync(0xFFFFFFFFu, c, off));
        if (c == 0x7FFFFFFF) break;
        if (lane == 0) keep[cnt] = c;
        cnt++;
        if (cnt >= MAXDET) break;   // num_det caps at 100; outputs only need first 100 kept
        r0 |= g_mask[(size_t)c * 64 + lane];
        r1 |= g_mask[(size_t)c * 64 + 32 + lane];
        int w = c >> 6;
        unsigned long long sb = 1ull << (c & 63);
        if (w == w0) r0 |= sb;
        else if (w == w1) r1 |= sb;
    }
    __syncwarp();
    // zero output, then scatter
    for (int k = lane; k < out_size; k += 32) out[k] = 0.0f;
    __syncwarp();
    int nw = min(cnt, MAXDET);
    for (int s = lane; s < nw; s += 32) {
        int j = keep[s];
        float4 b = g_cbox[j];
        out[s * 4 + 0] = b.x;
        out[s * 4 + 1] = b.y;
        out[s * 4 + 2] = b.z;
        out[s * 4 + 3] = b.w;
        out[4 * MAXDET + s] = g_cscore[j];
        out[5 * MAXDET + s] = (float)g_ccls[j];
    }
    if (lane == 0 && out_size > 6 * MAXDET) out[6 * MAXDET] = (float)nw;
}

// ---------------- launcher ----------------
extern "C" void kernel_launch(void* const* d_in, const int* in_sizes, int n_in,
                              void* d_out, int out_size) {
    const float* reg = (const float*)d_in[1];
    const float* cls = (const float*)d_in[2];
    const float* anc = (const float*)d_in[3];
    int N = in_sizes[1] / 4;
    int C = (int)((long long)in_sizes[2] / N);
    int HW = in_sizes[0] / 3;
    int side = (int)(sqrt((double)HW) + 0.5);
    float Wm1 = (float)(side - 1);
    float Hm1 = (float)(side - 1);

    k_zero<<<(65536 + 255) / 256, 256>>>();
    k_prep<<<(N + 255) / 256, 256>>>(reg, cls, anc, N, C, Wm1, Hm1);
    k_find<<<1, 1024>>>(0);
    k_hist2<<<(N + 255) / 256, 256>>>(N);
    k_find<<<1, 1024>>>(1);
    k_compact<<<(N + 255) / 256, 256>>>(N);
    k_fill_eq<<<1, 256>>>();
    k_sort<<<1, 1024>>>();
    k_gather<<<(KTOP + 255) / 256, 256>>>();
    k_mask<<<dim3(64, 64), 64>>>();
    k_scan<<<1, 32>>>((float*)d_out, out_size);
}

// round 2
// speedup vs baseline: 1.0507x; 1.0507x over previous
#include <cuda_runtime.h>
#include <stdint.h>
#include <math.h>

#define MAXN    131072
#define KTOP    4096
#define MAXDET  100
#define THRESH  0.5f
#define NMSTHR  0.5f

// ---------------- static device scratch (no allocations allowed) ----------------
__device__ float              g_score[MAXN];
__device__ unsigned int       g_key[MAXN];
__device__ float4             g_box[MAXN];
__device__ int                g_cls[MAXN];
__device__ __align__(16) int  g_hist1[65536];
__device__ __align__(16) int  g_hist2[65536];
__device__ int                g_cnt[4];          // [0]=cnt_gt, [1]=cnt_eq
__device__ int                g_selinfo[2];      // [0]=bucket B, [1]=count above bucket
__device__ unsigned int       g_Tkey;
__device__ int                g_G;
__device__ unsigned long long g_sel[KTOP];       // composite (key<<32)|~idx
__device__ int                g_eq[KTOP];
__device__ float4             g_cbox[KTOP];
__device__ float              g_cscore[KTOP];
__device__ int                g_ccls[KTOP];
__device__ unsigned long long g_mask[(size_t)KTOP * 64];

__device__ __forceinline__ unsigned int fkey(float f) {
    unsigned int u = __float_as_uint(f);
    return u ^ ((u >> 31) ? 0xFFFFFFFFu : 0x80000000u);
}

// ---------------- kernel 1: warp-per-anchor argmax + decode + histogram ----------------
// Coalesced: lane l reads cls[i*C + l], l+32, l+64.
__global__ void k_prep(const float* __restrict__ reg, const float* __restrict__ cls,
                       const float* __restrict__ anc, int N, int C, float Wm1, float Hm1) {
    int gw = (blockIdx.x * blockDim.x + threadIdx.x) >> 5;
    int lane = threadIdx.x & 31;
    if (gw >= N) return;
    int i = gw;

    const float* row = cls + (size_t)i * C;
    float best = -1e30f; int bc = 0x7FFFFFFF;
    for (int k = lane; k < C; k += 32) {
        float v = row[k];
        if (v > best) { best = v; bc = k; }   // ascending k => first occurrence kept
    }
#pragma unroll
    for (int off = 16; off; off >>= 1) {
        float ov = __shfl_down_sync(0xFFFFFFFFu, best, off);
        int   oi = __shfl_down_sync(0xFFFFFFFFu, bc, off);
        if (ov > best || (ov == best && oi < bc)) { best = ov; bc = oi; }
    }

    if (lane == 0) {
        float4 a = reinterpret_cast<const float4*>(anc)[i];
        float4 r = reinterpret_cast<const float4*>(reg)[i];
        float ya = (a.x + a.z) * 0.5f, xa = (a.y + a.w) * 0.5f;
        float ha = a.z - a.x, wa = a.w - a.y;
        float w = expf(r.w) * wa, h = expf(r.z) * ha;
        float yc = r.x * ha + ya, xc = r.y * wa + xa;
        float x1 = fmaxf(xc - w * 0.5f, 0.0f);
        float y1 = fmaxf(yc - h * 0.5f, 0.0f);
        float x2 = fminf(xc + w * 0.5f, Wm1);
        float y2 = fminf(yc + h * 0.5f, Hm1);
        g_box[i] = make_float4(x1, y1, x2, y2);

        float cand = (best > THRESH) ? best : -1.0f;
        g_score[i] = cand;
        g_cls[i] = bc;
        unsigned int k = fkey(cand);
        g_key[i] = k;
        atomicAdd(&g_hist1[k >> 16], 1);
    }
}

// ---------------- kernel 2/4: find bucket containing K-th largest (vectorized) ----------------
__global__ void k_find(int level) {
    __shared__ int seg[1024];
    __shared__ int suf[1024];
    const int*  hist  = (level == 0) ? g_hist1 : g_hist2;
    const int4* hist4 = reinterpret_cast<const int4*>(hist);
    int base = (level == 0) ? 0 : g_selinfo[1];
    int t = threadIdx.x;
    int s = 0;
#pragma unroll
    for (int j = 0; j < 16; j++) {
        int4 v = hist4[t * 16 + j];
        s += v.x + v.y + v.z + v.w;
    }
    seg[t] = s; suf[t] = s;
    __syncthreads();
    for (int off = 1; off < 1024; off <<= 1) {
        int v = (t + off < 1024) ? suf[t + off] : 0;
        __syncthreads();
        suf[t] += v;
        __syncthreads();
    }
    int exc = (t < 1023) ? suf[t + 1] : 0;
    int cg = exc + base;
    if (cg < KTOP && cg + seg[t] >= KTOP) {
        int b0 = t * 64;
        int acc = cg;
        for (int b = b0 + 63; b >= b0; b--) {
            int h = hist[b];
            if (acc < KTOP && acc + h >= KTOP) {
                if (level == 0) { g_selinfo[0] = b; g_selinfo[1] = acc; }
                else { g_Tkey = ((unsigned int)g_selinfo[0] << 16) | (unsigned int)b; g_G = acc; }
                break;
            }
            acc += h;
        }
    }
}

// ---------------- kernel 3: second-level histogram (+ self-clean hist1) ----------------
__global__ void k_hist2(int N) {
    int i = blockIdx.x * blockDim.x + threadIdx.x;
    if (i < 65536) g_hist1[i] = 0;   // consumed by k_find(0); reset for next replay
    if (i >= N) return;
    unsigned int k = g_key[i];
    if ((int)(k >> 16) == g_selinfo[0]) atomicAdd(&g_hist2[k & 0xFFFFu], 1);
}

// ---------------- kernel 5: compaction (+ self-clean hist2) ----------------
__global__ void k_compact(int N) {
    int i = blockIdx.x * blockDim.x + threadIdx.x;
    if (i < 65536) g_hist2[i] = 0;   // consumed by k_find(1); reset for next replay
    if (i >= N) return;
    unsigned int k = g_key[i];
    unsigned int T = g_Tkey;
    if (k > T) {
        int p = atomicAdd(&g_cnt[0], 1);
        g_sel[p] = ((unsigned long long)k << 32) | (unsigned int)(~(unsigned int)i);
    } else if (k == T) {
        int p = atomicAdd(&g_cnt[1], 1);
        if (p < KTOP) g_eq[p] = i;
    }
}

// ---------------- kernel 6: fill equal-key slots (lowest indices first) ----------------
__global__ void k_fill_eq() {
    __shared__ int red[256];
    int t = threadIdx.x;
    int need = KTOP - g_G;
    int E = g_cnt[1]; if (E > KTOP) E = KTOP;
    unsigned int T = g_Tkey;
    for (int r = 0; r < need; r++) {
        int m = 0x7FFFFFFF;
        for (int j = t; j < E; j += 256) m = min(m, g_eq[j]);
        red[t] = m;
        __syncthreads();
        for (int off = 128; off; off >>= 1) {
            if (t < off) red[t] = min(red[t], red[t + off]);
            __syncthreads();
        }
        int minv = red[0];
        for (int j = t; j < E; j += 256) if (g_eq[j] == minv) g_eq[j] = 0x7FFFFFFF;
        if (t == 0) g_sel[g_G + r] = ((unsigned long long)T << 32) | (unsigned int)(~(unsigned int)minv);
        __syncthreads();
    }
}

// ---------------- kernel 7: rank-by-counting sort + gather (+ clean counters) ----------------
// Composite keys are unique => rank = #{keys > mine} is a perfect permutation.
__global__ void k_rank() {
    __shared__ unsigned long long tile[256];
    int t = threadIdx.x;
    int me = blockIdx.x * 256 + t;
    unsigned long long my = g_sel[me];
    int rank = 0;
    for (int base = 0; base < KTOP; base += 256) {
        tile[t] = g_sel[base + t];
        __syncthreads();
#pragma unroll 8
        for (int j = 0; j < 256; j++) rank += (tile[j] > my);
        __syncthreads();
    }
    int idx = (int)(~(unsigned int)my);
    g_cbox[rank] = g_box[idx];
    g_cscore[rank] = g_score[idx];
    g_ccls[rank] = g_cls[idx];
    if (me == 0) { g_cnt[0] = 0; g_cnt[1] = 0; }   // reset for next replay
}

// ---------------- kernel 8: NMS suppression bitmask (4096x4096) ----------------
__global__ void k_mask() {
    __shared__ float4 cb[64];
    int t = threadIdx.x;
    int col0 = blockIdx.x * 64;
    int i = blockIdx.y * 256 + t;
    if (t < 64) cb[t] = g_cbox[col0 + t];
    __syncthreads();
    float4 bi = g_cbox[i];
    float areai = fmaxf(bi.z - bi.x, 0.0f) * fmaxf(bi.w - bi.y, 0.0f);
    unsigned long long bits = 0;
#pragma unroll 4
    for (int c = 0; c < 64; c++) {
        int j = col0 + c;
        if (j > i) {
            float4 bj = cb[c];
            float ix1 = fmaxf(bi.x, bj.x), iy1 = fmaxf(bi.y, bj.y);
            float ix2 = fminf(bi.z, bj.z), iy2 = fminf(bi.w, bj.w);
            float inter = fmaxf(ix2 - ix1, 0.0f) * fmaxf(iy2 - iy1, 0.0f);
            float areaj = fmaxf(bj.z - bj.x, 0.0f) * fmaxf(bj.w - bj.y, 0.0f);
            float uni = areai + areaj - inter;
            float iou = inter / fmaxf(uni, 1e-8f);
            if (iou > NMSTHR) bits |= 1ull << c;
        }
    }
    g_mask[(size_t)i * 64 + blockIdx.x] = bits;
}

// ---------------- kernel 9: sequential greedy scan (1 warp) + output ----------------
__global__ void k_scan(float* __restrict__ out, int out_size) {
    int lane = threadIdx.x;
    __shared__ int keep[MAXDET];
    unsigned long long r0 = 0, r1 = 0;
    int w0 = lane, w1 = lane + 32;
    for (int b = 0; b < 64; b++) {
        if (g_cscore[w0 * 64 + b] <= THRESH) r0 |= 1ull << b;
        if (g_cscore[w1 * 64 + b] <= THRESH) r1 |= 1ull << b;
    }
    int cnt = 0;
    while (true) {
        unsigned long long m0 = ~r0, m1 = ~r1;
        int c0 = m0 ? (w0 * 64 + (__ffsll((long long)m0) - 1)) : 0x7FFFFFFF;
        int c1 = m1 ? (w1 * 64 + (__ffsll((long long)m1) - 1)) : 0x7FFFFFFF;
        int c = min(c0, c1);
#pragma unroll
        for (int off = 16; off; off >>= 1) c = min(c, __shfl_xor_sync(0xFFFFFFFFu, c, off));
        if (c == 0x7FFFFFFF) break;
        if (lane == 0) keep[cnt] = c;
        cnt++;
        if (cnt >= MAXDET) break;
        r0 |= g_mask[(size_t)c * 64 + lane];
        r1 |= g_mask[(size_t)c * 64 + 32 + lane];
        int w = c >> 6;
        unsigned long long sb = 1ull << (c & 63);
        if (w == w0) r0 |= sb;
        else if (w == w1) r1 |= sb;
    }
    __syncwarp();
    for (int k = lane; k < out_size; k += 32) out[k] = 0.0f;
    __syncwarp();
    int nw = min(cnt, MAXDET);
    for (int s = lane; s < nw; s += 32) {
        int j = keep[s];
        float4 b = g_cbox[j];
        out[s * 4 + 0] = b.x;
        out[s * 4 + 1] = b.y;
        out[s * 4 + 2] = b.z;
        out[s * 4 + 3] = b.w;
        out[4 * MAXDET + s] = g_cscore[j];
        out[5 * MAXDET + s] = (float)g_ccls[j];
    }
    if (lane == 0 && out_size > 6 * MAXDET) out[6 * MAXDET] = (float)nw;
}

// ---------------- launcher ----------------
extern "C" void kernel_launch(void* const* d_in, const int* in_sizes, int n_in,
                              void* d_out, int out_size) {
    const float* reg = (const float*)d_in[1];
    const float* cls = (const float*)d_in[2];
    const float* anc = (const float*)d_in[3];
    int N = in_sizes[1] / 4;
    int C = (int)((long long)in_sizes[2] / N);
    int HW = in_sizes[0] / 3;
    int side = (int)(sqrt((double)HW) + 0.5);
    float Wm1 = (float)(side - 1);
    float Hm1 = (float)(side - 1);

    int warps_per_block = 8;                       // 256 threads
    int prep_blocks = (N + warps_per_block - 1) / warps_per_block;

    k_prep<<<prep_blocks, 256>>>(reg, cls, anc, N, C, Wm1, Hm1);
    k_find<<<1, 1024>>>(0);
    k_hist2<<<(N + 255) / 256, 256>>>(N);
    k_find<<<1, 1024>>>(1);
    k_compact<<<(N + 255) / 256, 256>>>(N);
    k_fill_eq<<<1, 256>>>();
    k_rank<<<KTOP / 256, 256>>>();
    k_mask<<<dim3(64, 16), 256>>>();
    k_scan<<<1, 32>>>((float*)d_out, out_size);
}